// round 1
// baseline (speedup 1.0000x reference)
#include <cuda_runtime.h>
#include <math.h>

#define SEQ 2048
#define HID 2048
#define HD  128
#define NH  16
#define NKV 4
#define EPSV 1e-6f

// ---------------- scratch (static device globals; no allocation) -------------
__device__ float g_Q[SEQ * HID];        // [s][h*128+d]
__device__ float g_K[SEQ * NKV * HD];   // [s][kv*128+d]
__device__ float g_V[SEQ * NKV * HD];
__device__ float g_AO[SEQ * HID];       // attention output
__device__ float g_Y[SEQ * HID];        // after Wo

// ---------------- SGEMM: C[M,N] = A[M,K] @ B[K,N], all row-major -------------
// 128x128 block tile, k-tile 16, 256 threads, 8x8 per-thread.
__global__ __launch_bounds__(256) void sgemm_kernel(
    const float* __restrict__ A, const float* __restrict__ B,
    float* __restrict__ C, int M, int N, int K)
{
    __shared__ float As[16][132];   // transposed A tile: As[k][m]
    __shared__ float Bs[16][128];   // Bs[k][n]
    int t  = threadIdx.x;
    int bm = blockIdx.y * 128, bn = blockIdx.x * 128;
    int ty = t >> 4, tx = t & 15;

    float acc[8][8];
#pragma unroll
    for (int i = 0; i < 8; i++)
#pragma unroll
        for (int j = 0; j < 8; j++) acc[i][j] = 0.0f;

    for (int k0 = 0; k0 < K; k0 += 16) {
#pragma unroll
        for (int i = 0; i < 2; i++) {
            int idx = i * 256 + t;            // 0..511 -> 128 rows x 4 float4
            int m = idx >> 2, k4 = (idx & 3) * 4;
            float4 a = *(const float4*)&A[(size_t)(bm + m) * K + k0 + k4];
            As[k4 + 0][m] = a.x; As[k4 + 1][m] = a.y;
            As[k4 + 2][m] = a.z; As[k4 + 3][m] = a.w;
        }
#pragma unroll
        for (int i = 0; i < 2; i++) {
            int idx = i * 256 + t;            // 0..511 -> 16 k x 32 float4
            int kk = idx >> 5, n4 = (idx & 31) * 4;
            *(float4*)&Bs[kk][n4] = *(const float4*)&B[(size_t)(k0 + kk) * N + bn + n4];
        }
        __syncthreads();
#pragma unroll
        for (int kk = 0; kk < 16; kk++) {
            float a[8], b[8];
            *(float4*)&a[0] = *(float4*)&As[kk][ty * 8];
            *(float4*)&a[4] = *(float4*)&As[kk][ty * 8 + 4];
            *(float4*)&b[0] = *(float4*)&Bs[kk][tx * 8];
            *(float4*)&b[4] = *(float4*)&Bs[kk][tx * 8 + 4];
#pragma unroll
            for (int i = 0; i < 8; i++)
#pragma unroll
                for (int j = 0; j < 8; j++)
                    acc[i][j] += a[i] * b[j];
        }
        __syncthreads();
    }
#pragma unroll
    for (int i = 0; i < 8; i++) {
        size_t row = (size_t)(bm + ty * 8 + i);
#pragma unroll
        for (int j = 0; j < 8; j += 4) {
            float4 v = make_float4(acc[i][j], acc[i][j+1], acc[i][j+2], acc[i][j+3]);
            *(float4*)&C[row * N + bn + tx * 8 + j] = v;
        }
    }
}

// -------- per-head RMSNorm + RoPE on Q (16 heads) and K (4 heads), in-place --
__global__ void norm_rope_kernel(const float* __restrict__ cosT,
                                 const float* __restrict__ sinT,
                                 const float* __restrict__ qscale,
                                 const float* __restrict__ kscale)
{
    int s = blockIdx.x;
    int h = blockIdx.y;   // 0..15 => Q, 16..19 => K
    int d = threadIdx.x;  // 0..127

    float* base;
    const float* sc;
    if (h < NH) { base = g_Q + (size_t)s * HID + h * HD;        sc = qscale; }
    else        { base = g_K + (size_t)s * (NKV*HD) + (h-NH)*HD; sc = kscale; }

    float x = base[d];
    float v = x * x;
#pragma unroll
    for (int m = 16; m > 0; m >>= 1) v += __shfl_xor_sync(0xffffffffu, v, m);

    __shared__ float ws[4];
    __shared__ float rn[HD];
    if ((d & 31) == 0) ws[d >> 5] = v;
    __syncthreads();
    float tot = ws[0] + ws[1] + ws[2] + ws[3];
    float inv = rsqrtf(tot * (1.0f / HD) + EPSV);

    float r = x * inv * sc[d];
    rn[d] = r;
    __syncthreads();
    float rot = (d < 64) ? -rn[d + 64] : rn[d - 64];
    float c  = cosT[(size_t)s * HD + d];
    float sn = sinT[(size_t)s * HD + d];
    base[d] = r * c + rot * sn;
}

// ---------------- causal GQA flash attention, fp32 ---------------------------
// grid (32 qblocks, 16 heads), 256 threads. Tiles 64x64, head_dim 128.
// Thread t: rg = t/16 owns rows rg*4..+3; score cols cg*4..+3; PV dims cg*8..+7
#define QT_P 68
#define VS_P 132
#define ATT_SMEM_FLOATS (128*QT_P /*QsT*/ + 128*QT_P /*KsT*/ + 64*VS_P /*Vs*/ + 64*QT_P /*Ps*/)

__global__ __launch_bounds__(256) void attn_kernel(float* __restrict__ O)
{
    extern __shared__ float sm[];
    float* QsT = sm;                    // [128][68]  QsT[d][r]
    float* KsT = QsT + 128 * QT_P;      // [128][68]  KsT[d][j]
    float* Vs  = KsT + 128 * QT_P;      // [64][132]  Vs[j][d]
    float* Ps  = Vs  + 64  * VS_P;      // [64][68]   Ps[r][j]

    int qb = blockIdx.x, h = blockIdx.y;
    int kv = h >> 2;
    int t  = threadIdx.x;
    int rg = t >> 4, cg = t & 15;
    const float scale = 0.08838834764831845f; // 1/sqrt(128)

    // fill QsT (transposed)
    const float* Qb = g_Q + (size_t)(qb * 64) * HID + h * HD;
#pragma unroll
    for (int i = 0; i < 8; i++) {
        int idx = i * 256 + t;          // 0..2047
        int r = idx >> 5, d4 = idx & 31;
        float4 q = *(const float4*)&Qb[(size_t)r * HID + d4 * 4];
        QsT[(d4*4 + 0) * QT_P + r] = q.x;
        QsT[(d4*4 + 1) * QT_P + r] = q.y;
        QsT[(d4*4 + 2) * QT_P + r] = q.z;
        QsT[(d4*4 + 3) * QT_P + r] = q.w;
    }

    float m[4], l[4], acc[4][8];
#pragma unroll
    for (int i = 0; i < 4; i++) {
        m[i] = -1e30f; l[i] = 0.0f;
#pragma unroll
        for (int dd = 0; dd < 8; dd++) acc[i][dd] = 0.0f;
    }

    for (int kb = 0; kb <= qb; kb++) {
        __syncthreads();   // previous PV done with Vs/Ps
        const float* Kb = g_K + (size_t)(kb * 64) * (NKV*HD) + kv * HD;
        const float* Vb = g_V + (size_t)(kb * 64) * (NKV*HD) + kv * HD;
#pragma unroll
        for (int i = 0; i < 8; i++) {
            int idx = i * 256 + t;
            int r = idx >> 5, d4 = idx & 31;
            float4 kk = *(const float4*)&Kb[(size_t)r * (NKV*HD) + d4 * 4];
            KsT[(d4*4 + 0) * QT_P + r] = kk.x;
            KsT[(d4*4 + 1) * QT_P + r] = kk.y;
            KsT[(d4*4 + 2) * QT_P + r] = kk.z;
            KsT[(d4*4 + 3) * QT_P + r] = kk.w;
            float4 vv = *(const float4*)&Vb[(size_t)r * (NKV*HD) + d4 * 4];
            *(float4*)&Vs[r * VS_P + d4 * 4] = vv;
        }
        __syncthreads();

        // scores: s[i][j] = Q[rg*4+i] . K[cg*4+j]
        float s[4][4];
#pragma unroll
        for (int i = 0; i < 4; i++)
#pragma unroll
            for (int j = 0; j < 4; j++) s[i][j] = 0.0f;
#pragma unroll 8
        for (int d = 0; d < 128; d++) {
            float4 qv = *(float4*)&QsT[d * QT_P + rg * 4];
            float4 kw = *(float4*)&KsT[d * QT_P + cg * 4];
            s[0][0] += qv.x * kw.x; s[0][1] += qv.x * kw.y; s[0][2] += qv.x * kw.z; s[0][3] += qv.x * kw.w;
            s[1][0] += qv.y * kw.x; s[1][1] += qv.y * kw.y; s[1][2] += qv.y * kw.z; s[1][3] += qv.y * kw.w;
            s[2][0] += qv.z * kw.x; s[2][1] += qv.z * kw.y; s[2][2] += qv.z * kw.z; s[2][3] += qv.z * kw.w;
            s[3][0] += qv.w * kw.x; s[3][1] += qv.w * kw.y; s[3][2] += qv.w * kw.z; s[3][3] += qv.w * kw.w;
        }
#pragma unroll
        for (int i = 0; i < 4; i++)
#pragma unroll
            for (int j = 0; j < 4; j++) s[i][j] *= scale;

        if (kb == qb) {   // causal mask inside diagonal block
#pragma unroll
            for (int i = 0; i < 4; i++)
#pragma unroll
                for (int j = 0; j < 4; j++)
                    if (cg * 4 + j > rg * 4 + i) s[i][j] = -1e30f;
        }

        // row max over 64 cols (16 lanes x 4 local)
        float rm[4];
#pragma unroll
        for (int i = 0; i < 4; i++)
            rm[i] = fmaxf(fmaxf(s[i][0], s[i][1]), fmaxf(s[i][2], s[i][3]));
#pragma unroll
        for (int msk = 8; msk > 0; msk >>= 1)
#pragma unroll
            for (int i = 0; i < 4; i++)
                rm[i] = fmaxf(rm[i], __shfl_xor_sync(0xffffffffu, rm[i], msk));

        float corr[4];
#pragma unroll
        for (int i = 0; i < 4; i++) {
            float nm = fmaxf(m[i], rm[i]);
            corr[i] = __expf(m[i] - nm);
            m[i] = nm;
        }

        float rs[4] = {0.f, 0.f, 0.f, 0.f};
#pragma unroll
        for (int i = 0; i < 4; i++)
#pragma unroll
            for (int j = 0; j < 4; j++) {
                float p = __expf(s[i][j] - m[i]);
                Ps[(rg * 4 + i) * QT_P + cg * 4 + j] = p;
                rs[i] += p;
            }
#pragma unroll
        for (int msk = 8; msk > 0; msk >>= 1)
#pragma unroll
            for (int i = 0; i < 4; i++)
                rs[i] += __shfl_xor_sync(0xffffffffu, rs[i], msk);
#pragma unroll
        for (int i = 0; i < 4; i++) {
            l[i] = l[i] * corr[i] + rs[i];
#pragma unroll
            for (int dd = 0; dd < 8; dd++) acc[i][dd] *= corr[i];
        }
        __syncthreads();  // Ps fully written

        // PV: acc[i][dd] += P[row][j] * V[j][cg*8+dd]
#pragma unroll 4
        for (int j = 0; j < 64; j++) {
            float4 v0 = *(float4*)&Vs[j * VS_P + cg * 8];
            float4 v1 = *(float4*)&Vs[j * VS_P + cg * 8 + 4];
#pragma unroll
            for (int i = 0; i < 4; i++) {
                float p = Ps[(rg * 4 + i) * QT_P + j];
                acc[i][0] += p * v0.x; acc[i][1] += p * v0.y;
                acc[i][2] += p * v0.z; acc[i][3] += p * v0.w;
                acc[i][4] += p * v1.x; acc[i][5] += p * v1.y;
                acc[i][6] += p * v1.z; acc[i][7] += p * v1.w;
            }
        }
    }

    float* Ob = O + (size_t)(qb * 64) * HID + h * HD;
#pragma unroll
    for (int i = 0; i < 4; i++) {
        float invl = 1.0f / l[i];
        float4 o0 = make_float4(acc[i][0]*invl, acc[i][1]*invl, acc[i][2]*invl, acc[i][3]*invl);
        float4 o1 = make_float4(acc[i][4]*invl, acc[i][5]*invl, acc[i][6]*invl, acc[i][7]*invl);
        size_t row = (size_t)(rg * 4 + i);
        *(float4*)&Ob[row * HID + cg * 8]     = o0;
        *(float4*)&Ob[row * HID + cg * 8 + 4] = o1;
    }
}

// ---------------- final RMSNorm over hidden=2048 -----------------------------
__global__ void final_norm_kernel(const float* __restrict__ sc, float* __restrict__ out)
{
    int s = blockIdx.x;
    const float* y = g_Y + (size_t)s * HID;
    float v = 0.0f;
    for (int d = threadIdx.x; d < HID; d += 256) { float x = y[d]; v += x * x; }
#pragma unroll
    for (int m = 16; m > 0; m >>= 1) v += __shfl_xor_sync(0xffffffffu, v, m);
    __shared__ float ws[8];
    if ((threadIdx.x & 31) == 0) ws[threadIdx.x >> 5] = v;
    __syncthreads();
    float tot = 0.0f;
#pragma unroll
    for (int i = 0; i < 8; i++) tot += ws[i];
    float inv = rsqrtf(tot * (1.0f / HID) + EPSV);
    for (int d = threadIdx.x; d < HID; d += 256)
        out[(size_t)s * HID + d] = y[d] * inv * sc[d];
}

// ---------------- launch -----------------------------------------------------
extern "C" void kernel_launch(void* const* d_in, const int* in_sizes, int n_in,
                              void* d_out, int out_size)
{
    const float* hidden = (const float*)d_in[0];
    const float* cosT   = (const float*)d_in[1];
    const float* sinT   = (const float*)d_in[2];
    const float* Wq     = (const float*)d_in[3];
    const float* Wk     = (const float*)d_in[4];
    const float* Wv     = (const float*)d_in[5];
    const float* Wo     = (const float*)d_in[6];
    const float* qs     = (const float*)d_in[7];
    const float* ks     = (const float*)d_in[8];
    const float* ls     = (const float*)d_in[9];
    float* out = (float*)d_out;

    float *Qp, *Kp, *Vp, *AOp, *Yp;
    cudaGetSymbolAddress((void**)&Qp,  g_Q);
    cudaGetSymbolAddress((void**)&Kp,  g_K);
    cudaGetSymbolAddress((void**)&Vp,  g_V);
    cudaGetSymbolAddress((void**)&AOp, g_AO);
    cudaGetSymbolAddress((void**)&Yp,  g_Y);

    // QKV projections
    sgemm_kernel<<<dim3(HID/128, SEQ/128), 256>>>(hidden, Wq, Qp, SEQ, HID, HID);
    sgemm_kernel<<<dim3((NKV*HD)/128, SEQ/128), 256>>>(hidden, Wk, Kp, SEQ, NKV*HD, HID);
    sgemm_kernel<<<dim3((NKV*HD)/128, SEQ/128), 256>>>(hidden, Wv, Vp, SEQ, NKV*HD, HID);

    // per-head RMSNorm + RoPE
    norm_rope_kernel<<<dim3(SEQ, NH + NKV), HD>>>(cosT, sinT, qs, ks);

    // causal GQA attention
    static_assert(ATT_SMEM_FLOATS * 4 < 227 * 1024, "smem");
    cudaFuncSetAttribute(attn_kernel, cudaFuncAttributeMaxDynamicSharedMemorySize,
                         ATT_SMEM_FLOATS * 4);
    attn_kernel<<<dim3(SEQ/64, NH), 256, ATT_SMEM_FLOATS * 4>>>(AOp);

    // output projection
    sgemm_kernel<<<dim3(HID/128, SEQ/128), 256>>>(AOp, Wo, Yp, SEQ, HID, HID);

    // final RMSNorm -> d_out
    final_norm_kernel<<<SEQ, 256>>>(ls, out);
}